// round 1
// baseline (speedup 1.0000x reference)
#include <cuda_runtime.h>
#include <cuda_bf16.h>

// VectorQuantizer, D=1, N=512, x: [8,16,64,64] fp32.
// Strategy: sort codebook once (bitonic, 1 block), then per-element nearest
// value via 9-step branchless binary search in smem. Faithful replication of
// the reference's permutation bug: out[b,c,h,w] = q(x_flat[j]),
// j = ((b*H+h)*W+w)*C + c. Losses: mean((x - quantized)^2), written twice.

#define BQ 8
#define CQ 16
#define HQ 64
#define WQ 64
#define NCODE 512
#define NELEM (BQ*CQ*HQ*WQ)   // 524288

__device__ float g_sorted[NCODE];
__device__ float g_partial[BQ * HQ];   // 512 per-block partial loss sums

// ---------------- Kernel 1: bitonic sort of 512 codebook values ----------------
__global__ void vq_sort_kernel(const float* __restrict__ w) {
    __shared__ float s[NCODE];
    int t = threadIdx.x;
    s[t] = w[t];
    __syncthreads();
    for (int k = 2; k <= NCODE; k <<= 1) {
        for (int j = k >> 1; j > 0; j >>= 1) {
            int ixj = t ^ j;
            if (ixj > t) {
                float a = s[t], b = s[ixj];
                bool up = ((t & k) == 0);
                if ((a > b) == up) { s[t] = b; s[ixj] = a; }
            }
            __syncthreads();
        }
    }
    g_sorted[t] = s[t];
}

// ---------------- Kernel 2: quantize + permute + partial loss ----------------
// grid = B*H = 512 blocks, 1024 threads. Block bid handles b = bid/64, h = bid%64.
// Source slice: j in [bid*1024, bid*1024+1024) contiguous in x.
// j decodes as c = j%16, w = (j/16)%64 within this (b,h).
__global__ __launch_bounds__(1024) void vq_main_kernel(const float* __restrict__ x,
                                                       float* __restrict__ out) {
    __shared__ float s_sorted[NCODE];
    __shared__ float s_tile[WQ * 17];   // padded transpose tile (conflict-free)
    __shared__ float s_warp[32];

    int tid = threadIdx.x;
    if (tid < NCODE) s_sorted[tid] = g_sorted[tid];

    int j = blockIdx.x * 1024 + tid;
    float v = x[j];
    __syncthreads();

    // branchless lower-bound: pos = #elements <= v, pos in [0,512]
    int pos = 0;
#pragma unroll
    for (int step = NCODE / 2; step >= 1; step >>= 1) {
        pos += (s_sorted[pos + step - 1] <= v) ? step : 0;
    }
    float q;
    if (pos == 0)            q = s_sorted[0];
    else if (pos == NCODE)   q = s_sorted[NCODE - 1];
    else {
        float lo = s_sorted[pos - 1], hi = s_sorted[pos];
        q = ((v - lo) <= (hi - v)) ? lo : hi;
    }

    // transpose within the (b,h) slice: source layout (w,c) c-inner -> dest c-outer
    int w = tid >> 4, c = tid & 15;        // j local = w*16 + c
    s_tile[w * 17 + c] = q;
    __syncthreads();

    int c2 = tid >> 6, w2 = tid & 63;
    float q2 = s_tile[w2 * 17 + c2];

    int b = blockIdx.x >> 6, h = blockIdx.x & 63;
    int i = b * (CQ * HQ * WQ) + c2 * (HQ * WQ) + h * WQ + w2;
    float xv = x[i];
    out[i] = xv + (q2 - xv);               // straight-through, literal replication
    float d = xv - q2;
    float acc = d * d;

    // block reduce (32 warps)
#pragma unroll
    for (int o = 16; o; o >>= 1) acc += __shfl_down_sync(0xffffffffu, acc, o);
    if ((tid & 31) == 0) s_warp[tid >> 5] = acc;
    __syncthreads();
    if (tid < 32) {
        float a = s_warp[tid];
#pragma unroll
        for (int o = 16; o; o >>= 1) a += __shfl_down_sync(0xffffffffu, a, o);
        if (tid == 0) g_partial[blockIdx.x] = a;
    }
}

// ---------------- Kernel 3: finalize losses ----------------
__global__ void vq_finalize_kernel(float* __restrict__ out, int nq) {
    __shared__ float s_warp[16];
    int t = threadIdx.x;                   // 512 threads
    float a = g_partial[t];
#pragma unroll
    for (int o = 16; o; o >>= 1) a += __shfl_down_sync(0xffffffffu, a, o);
    if ((t & 31) == 0) s_warp[t >> 5] = a;
    __syncthreads();
    if (t < 16) {
        float b = s_warp[t];
#pragma unroll
        for (int o = 8; o; o >>= 1) b += __shfl_down_sync(0xffffu, b, o);
        if (t == 0) {
            float mean = b / (float)NELEM;
            out[nq]     = mean;   // q_latent_loss
            out[nq + 1] = mean;   // e_latent_loss (identical value)
        }
    }
}

extern "C" void kernel_launch(void* const* d_in, const int* in_sizes, int n_in,
                              void* d_out, int out_size) {
    const float* x = (const float*)d_in[0];
    const float* w = (const float*)d_in[1];
    float* out = (float*)d_out;
    int nq = out_size - 2;   // quantized elements, then 2 loss scalars

    vq_sort_kernel<<<1, NCODE>>>(w);
    vq_main_kernel<<<BQ * HQ, 1024>>>(x, out);
    vq_finalize_kernel<<<1, BQ * HQ>>>(out, nq);
}